// round 10
// baseline (speedup 1.0000x reference)
#include <cuda_runtime.h>
#include <cuda_bf16.h>
#include <cstdint>

// Output = all-ones [2048,2048] f32 (reference encoder maps every sample to
// the e_0 basis state -> all pairwise fidelities are exactly 1).
//
// Findings so far: STG.256 (v8) + .cs is the best store mechanism; wall time
// has a clear minimum at 512 CTAs (256->7.36, 512->7.14, 1024->8.06 us; big
// grids inflate graph-replay launch cost despite better in-kernel time).
// R9 keeps 512 CTAs and doubles threads/CTA to 512 (2 v8-stores each) to
// double store-issue parallelism during the pipeline-fill ramp.

__global__ void __launch_bounds__(512, 4)
fill_ones_v8t512(float* __restrict__ out) {
    // Each block owns a contiguous 32 KB slab: 8192 floats.
    // Thread t covers [t*8, t*8+8) within each of 2 chunks of 4096 floats.
    float* p = out + (size_t)blockIdx.x * 8192 + threadIdx.x * 8;
    const float one = 1.0f;
    asm volatile(
        "st.global.cs.v8.f32 [%0], {%1, %1, %1, %1, %1, %1, %1, %1};"
        :: "l"(p), "f"(one) : "memory");
    asm volatile(
        "st.global.cs.v8.f32 [%0], {%1, %1, %1, %1, %1, %1, %1, %1};"
        :: "l"(p + 4096), "f"(one) : "memory");
}

// Generic fallback for sizes not matching the exact partition (unused here:
// 4,194,304 = 512 blocks * 8192 floats exactly).
__global__ void fill_ones_tail(float* __restrict__ out, int start, int n) {
    int i = start + blockIdx.x * blockDim.x + threadIdx.x;
    if (i < n) out[i] = 1.0f;
}

extern "C" void kernel_launch(void* const* d_in, const int* in_sizes, int n_in,
                              void* d_out, int out_size) {
    (void)d_in; (void)in_sizes; (void)n_in;
    float* out = (float*)d_out;

    const int elems_per_block = 8192;                 // 32 KB slab
    int full_blocks = out_size / elems_per_block;     // 512
    if (full_blocks > 0) {
        fill_ones_v8t512<<<full_blocks, 512>>>(out);
    }
    int done = full_blocks * elems_per_block;
    int rem = out_size - done;
    if (rem > 0) {
        int blocks = (rem + 255) / 256;
        fill_ones_tail<<<blocks, 256>>>(out, done, out_size);
    }
}

// round 12
// speedup vs baseline: 1.0039x; 1.0039x over previous
#include <cuda_runtime.h>
#include <cuda_bf16.h>
#include <cstdint>

// Output = all-ones [2048,2048] f32: the reference's encoder ignores the
// inputs and maps every sample to the e_0 basis state, so all pairwise
// fidelities |<s1_i|s2_j>|^2 are exactly 1. The problem reduces to a
// 16.78 MB constant fill.
//
// Session findings (R1-R10):
//  - Write path into L2 ceilings at ~2.8 TB/s on this part, shared across
//    scalar STG, TMA bulk, and their combination -> ~6us in-kernel floor.
//  - STG.256 (st.global.v8.f32) is the best mechanism (wall 8.2 -> 7.14us);
//    .cs streaming hint marginally ahead of default.
//  - Grid sweep: {256,512,1024,4096} CTAs x {256,512} threads -> optimum at
//    512 CTAs x 256 threads x 4 v8-stores (32 KB contiguous slab per CTA).
//  - R10 run failed on container infra, not the kernel; this is a resubmit
//    of the locked-in optimum (previously passed at 7.14-7.17us, rel_err 0).

__global__ void __launch_bounds__(256, 8)
fill_ones_v8cs(float* __restrict__ out) {
    // Each block owns a contiguous 32 KB slab: 256 threads x 128 B.
    // Thread t covers [t*8, t*8+8) within each of 4 chunks of 2048 floats;
    // each warp store = 1 KB contiguous, fully coalesced.
    float* p = out + (size_t)blockIdx.x * 8192 + threadIdx.x * 8;
    const float one = 1.0f;
#pragma unroll
    for (int i = 0; i < 4; i++) {
        asm volatile(
            "st.global.cs.v8.f32 [%0], {%1, %1, %1, %1, %1, %1, %1, %1};"
            :: "l"(p + i * 2048), "f"(one)
            : "memory");
    }
}

// Generic fallback for sizes not matching the exact partition (unused here:
// 4,194,304 = 512 blocks * 8192 floats exactly).
__global__ void fill_ones_tail(float* __restrict__ out, int start, int n) {
    int i = start + blockIdx.x * blockDim.x + threadIdx.x;
    if (i < n) out[i] = 1.0f;
}

extern "C" void kernel_launch(void* const* d_in, const int* in_sizes, int n_in,
                              void* d_out, int out_size) {
    (void)d_in; (void)in_sizes; (void)n_in;
    float* out = (float*)d_out;

    const int elems_per_block = 8192;                 // 32 KB slab
    int full_blocks = out_size / elems_per_block;     // 512
    if (full_blocks > 0) {
        fill_ones_v8cs<<<full_blocks, 256>>>(out);
    }
    int done = full_blocks * elems_per_block;
    int rem = out_size - done;
    if (rem > 0) {
        int blocks = (rem + 255) / 256;
        fill_ones_tail<<<blocks, 256>>>(out, done, out_size);
    }
}

// round 13
// speedup vs baseline: 1.1429x; 1.1384x over previous
#include <cuda_runtime.h>
#include <cuda_bf16.h>
#include <cstdint>

// Output = all-ones [2048,2048] f32: the reference's encoder ignores the
// inputs and maps every sample to the e_0 basis state, so all pairwise
// fidelities |<s1_i|s2_j>|^2 are exactly 1. The problem reduces to a
// 16.78 MB constant fill.
//
// Final session model (R1-R12):
//  - In-kernel time is pinned at ~6us across ALL mechanisms (STG.128 MLP1/8,
//    STG.256, TMA bulk, STG+TMA hybrid, .cs hints) and all grid shapes:
//    the global-write path sustains ~2.8 TB/s for write-once traffic and is
//    the hardware floor. Output stays L2-resident (DRAM 0%).
//  - Identical source measured 7.14us and 8.16us on different holds ->
//    cross-hold wall variance ~1us; config deltas inside that band are noise.
//  - This config (512 CTAs x 256 thr x 4 st.global.cs.v8.f32, contiguous
//    32KB slab/CTA, exact cover, single kernel node) holds the session's two
//    best measurements and is locked in as final.

__global__ void __launch_bounds__(256, 8)
fill_ones_v8cs(float* __restrict__ out) {
    // Each block owns a contiguous 32 KB slab: 256 threads x 128 B.
    // Thread t covers [t*8, t*8+8) within each of 4 chunks of 2048 floats;
    // each warp store = 1 KB contiguous, fully coalesced.
    float* p = out + (size_t)blockIdx.x * 8192 + threadIdx.x * 8;
    const float one = 1.0f;
#pragma unroll
    for (int i = 0; i < 4; i++) {
        asm volatile(
            "st.global.cs.v8.f32 [%0], {%1, %1, %1, %1, %1, %1, %1, %1};"
            :: "l"(p + i * 2048), "f"(one)
            : "memory");
    }
}

// Generic fallback for sizes not matching the exact partition (unused here:
// 4,194,304 = 512 blocks * 8192 floats exactly, so only one kernel node is
// ever captured).
__global__ void fill_ones_tail(float* __restrict__ out, int start, int n) {
    int i = start + blockIdx.x * blockDim.x + threadIdx.x;
    if (i < n) out[i] = 1.0f;
}

extern "C" void kernel_launch(void* const* d_in, const int* in_sizes, int n_in,
                              void* d_out, int out_size) {
    (void)d_in; (void)in_sizes; (void)n_in;
    float* out = (float*)d_out;

    const int elems_per_block = 8192;                 // 32 KB slab
    int full_blocks = out_size / elems_per_block;     // 512
    if (full_blocks > 0) {
        fill_ones_v8cs<<<full_blocks, 256>>>(out);
    }
    int done = full_blocks * elems_per_block;
    int rem = out_size - done;
    if (rem > 0) {
        int blocks = (rem + 255) / 256;
        fill_ones_tail<<<blocks, 256>>>(out, done, out_size);
    }
}